// round 1
// baseline (speedup 1.0000x reference)
#include <cuda_runtime.h>
#include <math.h>

// Problem constants (fixed by setup_inputs)
#define T_TOKENS 4096
#define H_DIM    1024
#define I_DIM    4096
#define N_EXP    8
#define TOPK     2
#define OUT_ELEMS  (T_TOKENS * H_DIM)            // 4,194,304
#define LOGITS_OFF OUT_ELEMS                     // router_logits [T, E]
#define AUX_OFF    (OUT_ELEMS + T_TOKENS * N_EXP)// aux_loss scalar
#define MAXROWS  (T_TOKENS * TOPK)               // 8192 dispatched rows

#define BM 64
#define BN 64
#define BK 16
#define MAXTILES 136   // worst case sum_e ceil(ne/64) <= 128 + 7

// ---------------- device scratch (no allocation allowed) ----------------
__device__ float g_hbuf[(size_t)MAXROWS * I_DIM];   // 128 MiB intermediate h
__device__ int   g_counts[N_EXP];
__device__ int   g_offsets[N_EXP];
__device__ int   g_cursor[N_EXP];
__device__ int   g_tok[MAXROWS];
__device__ float g_gate[MAXROWS];
__device__ int   g_top_idx[T_TOKENS * TOPK];
__device__ float g_top_gate[T_TOKENS * TOPK];
__device__ float g_accp[N_EXP];
__device__ float g_zsum;
__device__ int   g_tile_e[MAXTILES];
__device__ int   g_tile_m[MAXTILES];

// ---------------- init ----------------
__global__ void init_kernel() {
    int i = threadIdx.x;
    if (i < N_EXP) {
        g_counts[i] = 0;
        g_cursor[i] = 0;
        g_accp[i]   = 0.f;
    }
    if (i == 0) g_zsum = 0.f;
}

// ---------------- router: logits, top-2 gates, aux stats ----------------
__global__ void router_kernel(const float* __restrict__ x,
                              const float* __restrict__ wg,
                              float* __restrict__ out) {
    __shared__ float sl[N_EXP];
    const int t   = blockIdx.x;
    const int tid = threadIdx.x;
    if (tid < N_EXP) sl[tid] = 0.f;
    __syncthreads();

    float p[N_EXP];
#pragma unroll
    for (int e = 0; e < N_EXP; e++) p[e] = 0.f;

    const float* xr = x + (size_t)t * H_DIM;
    for (int h = tid; h < H_DIM; h += blockDim.x) {
        float xv = xr[h];
#pragma unroll
        for (int e = 0; e < N_EXP; e++) p[e] += xv * wg[h * N_EXP + e];
    }
    // warp reduce then smem atomics
#pragma unroll
    for (int off = 16; off > 0; off >>= 1) {
#pragma unroll
        for (int e = 0; e < N_EXP; e++)
            p[e] += __shfl_down_sync(0xffffffffu, p[e], off);
    }
    if ((tid & 31) == 0) {
#pragma unroll
        for (int e = 0; e < N_EXP; e++) atomicAdd(&sl[e], p[e]);
    }
    __syncthreads();

    if (tid == 0) {
        float l[N_EXP];
#pragma unroll
        for (int e = 0; e < N_EXP; e++) {
            l[e] = sl[e];
            out[LOGITS_OFF + t * N_EXP + e] = l[e];
        }
        // top-2 (stable: first index wins ties, matching lax.top_k)
        int i0 = 0; float v0 = l[0];
#pragma unroll
        for (int e = 1; e < N_EXP; e++) if (l[e] > v0) { v0 = l[e]; i0 = e; }
        int i1 = -1; float v1 = -1e30f;
#pragma unroll
        for (int e = 0; e < N_EXP; e++) if (e != i0 && l[e] > v1) { v1 = l[e]; i1 = e; }
        float g0 = 1.f / (1.f + expf(v1 - v0));
        float g1 = 1.f - g0;
        g_top_idx[2 * t]      = i0;  g_top_gate[2 * t]      = g0;
        g_top_idx[2 * t + 1]  = i1;  g_top_gate[2 * t + 1]  = g1;
        atomicAdd(&g_counts[i0], 1);
        atomicAdd(&g_counts[i1], 1);
        // full softmax for acc_probs + logsumexp for z-loss
        float m = l[0];
#pragma unroll
        for (int e = 1; e < N_EXP; e++) m = fmaxf(m, l[e]);
        float den = 0.f;
#pragma unroll
        for (int e = 0; e < N_EXP; e++) den += expf(l[e] - m);
#pragma unroll
        for (int e = 0; e < N_EXP; e++) atomicAdd(&g_accp[e], expf(l[e] - m) / den);
        float lse = m + logf(den);
        atomicAdd(&g_zsum, lse * lse);
    }
}

// ---------------- offsets + tile worklist ----------------
__global__ void build_kernel() {
    int off = 0;
    for (int e = 0; e < N_EXP; e++) { g_offsets[e] = off; off += g_counts[e]; }
    int gm = 0;
    for (int e = 0; e < N_EXP; e++) {
        int nt = (g_counts[e] + BM - 1) / BM;
        for (int i = 0; i < nt && gm < MAXTILES; i++) {
            g_tile_e[gm] = e; g_tile_m[gm] = i; gm++;
        }
    }
    for (; gm < MAXTILES; gm++) g_tile_e[gm] = -1;
}

// ---------------- scatter tokens into per-expert groups ----------------
__global__ void scatter_kernel() {
    int t = blockIdx.x * blockDim.x + threadIdx.x;
    if (t >= T_TOKENS) return;
#pragma unroll
    for (int k = 0; k < TOPK; k++) {
        int e   = g_top_idx[2 * t + k];
        int pos = atomicAdd(&g_cursor[e], 1);
        int idx = g_offsets[e] + pos;
        g_tok[idx]  = t;
        g_gate[idx] = g_top_gate[2 * t + k];
    }
}

// ---------------- GEMM1: h = gelu(x_gathered @ w_fc[e]^T + b_fc[e]) ----------------
__global__ __launch_bounds__(256) void gemm1_kernel(const float* __restrict__ x,
                                                    const float* __restrict__ w_fc,
                                                    const float* __restrict__ b_fc) {
    const int e = g_tile_e[blockIdx.y];
    if (e < 0) return;
    const int ne   = g_counts[e];
    const int base = g_offsets[e];
    const int row0 = g_tile_m[blockIdx.y] * BM;
    const int n0   = blockIdx.x * BN;
    const float* Bp = w_fc + (size_t)e * I_DIM * H_DIM;

    __shared__ float As[BM][BK + 1];
    __shared__ float Bs[BN][BK + 1];
    __shared__ int   toks[BM];

    const int tid = threadIdx.x;
    if (tid < BM) {
        int r = row0 + tid;
        toks[tid] = g_tok[base + (r < ne ? r : 0)];
    }
    __syncthreads();

    const int arow = tid >> 2;
    const int acol = (tid & 3) * 4;
    const int ty = tid >> 4, tx = tid & 15;
    const size_t a_base = (size_t)toks[arow] * H_DIM + acol;
    const size_t b_base = (size_t)(n0 + arow) * H_DIM + acol;

    float acc[4][4];
#pragma unroll
    for (int i = 0; i < 4; i++)
#pragma unroll
        for (int j = 0; j < 4; j++) acc[i][j] = 0.f;

    for (int k0 = 0; k0 < H_DIM; k0 += BK) {
        float4 av = *(const float4*)(x  + a_base + k0);
        float4 bv = *(const float4*)(Bp + b_base + k0);
        As[arow][acol] = av.x; As[arow][acol + 1] = av.y;
        As[arow][acol + 2] = av.z; As[arow][acol + 3] = av.w;
        Bs[arow][acol] = bv.x; Bs[arow][acol + 1] = bv.y;
        Bs[arow][acol + 2] = bv.z; Bs[arow][acol + 3] = bv.w;
        __syncthreads();
#pragma unroll
        for (int kk = 0; kk < BK; kk++) {
            float a[4], b[4];
#pragma unroll
            for (int i = 0; i < 4; i++) a[i] = As[ty * 4 + i][kk];
#pragma unroll
            for (int j = 0; j < 4; j++) b[j] = Bs[tx * 4 + j][kk];
#pragma unroll
            for (int i = 0; i < 4; i++)
#pragma unroll
                for (int j = 0; j < 4; j++) acc[i][j] += a[i] * b[j];
        }
        __syncthreads();
    }

#pragma unroll
    for (int i = 0; i < 4; i++) {
        int r = row0 + ty * 4 + i;
        if (r < ne) {
            size_t hrow = (size_t)(base + r) * I_DIM;
#pragma unroll
            for (int j = 0; j < 4; j++) {
                int c = n0 + tx * 4 + j;
                float v = acc[i][j] + b_fc[e * I_DIM + c];
                v = 0.5f * v * (1.0f + erff(v * 0.7071067811865476f));
                g_hbuf[hrow + c] = v;
            }
        }
    }
}

// ---------------- GEMM2: out += gate * (h @ w_proj[e]^T + b_proj[e]) ----------------
__global__ __launch_bounds__(256) void gemm2_kernel(const float* __restrict__ w_proj,
                                                    const float* __restrict__ b_proj,
                                                    float* __restrict__ out) {
    const int e = g_tile_e[blockIdx.y];
    if (e < 0) return;
    const int ne   = g_counts[e];
    const int base = g_offsets[e];
    const int row0 = g_tile_m[blockIdx.y] * BM;
    const int n0   = blockIdx.x * BN;
    const float* Bp = w_proj + (size_t)e * H_DIM * I_DIM;

    __shared__ float As[BM][BK + 1];
    __shared__ float Bs[BN][BK + 1];
    __shared__ int   toks[BM];
    __shared__ float sgate[BM];

    const int tid = threadIdx.x;
    if (tid < BM) {
        int r = row0 + tid;
        int rr = (r < ne ? r : 0);
        toks[tid]  = g_tok[base + rr];
        sgate[tid] = g_gate[base + rr];
    }
    __syncthreads();

    const int arow = tid >> 2;
    const int acol = (tid & 3) * 4;
    const int ty = tid >> 4, tx = tid & 15;
    int rA = row0 + arow; rA = (rA < ne ? rA : 0);
    const size_t a_base = (size_t)(base + rA) * I_DIM + acol;
    const size_t b_base = (size_t)(n0 + arow) * I_DIM + acol;

    float acc[4][4];
#pragma unroll
    for (int i = 0; i < 4; i++)
#pragma unroll
        for (int j = 0; j < 4; j++) acc[i][j] = 0.f;

    for (int k0 = 0; k0 < I_DIM; k0 += BK) {
        float4 av = *(const float4*)(g_hbuf + a_base + k0);
        float4 bv = *(const float4*)(Bp     + b_base + k0);
        As[arow][acol] = av.x; As[arow][acol + 1] = av.y;
        As[arow][acol + 2] = av.z; As[arow][acol + 3] = av.w;
        Bs[arow][acol] = bv.x; Bs[arow][acol + 1] = bv.y;
        Bs[arow][acol + 2] = bv.z; Bs[arow][acol + 3] = bv.w;
        __syncthreads();
#pragma unroll
        for (int kk = 0; kk < BK; kk++) {
            float a[4], b[4];
#pragma unroll
            for (int i = 0; i < 4; i++) a[i] = As[ty * 4 + i][kk];
#pragma unroll
            for (int j = 0; j < 4; j++) b[j] = Bs[tx * 4 + j][kk];
#pragma unroll
            for (int i = 0; i < 4; i++)
#pragma unroll
                for (int j = 0; j < 4; j++) acc[i][j] += a[i] * b[j];
        }
        __syncthreads();
    }

#pragma unroll
    for (int i = 0; i < 4; i++) {
        int r = row0 + ty * 4 + i;
        if (r < ne) {
            int   tok = toks[ty * 4 + i];
            float g   = sgate[ty * 4 + i];
#pragma unroll
            for (int j = 0; j < 4; j++) {
                int c = n0 + tx * 4 + j;
                float v = acc[i][j] + b_proj[e * H_DIM + c];
                atomicAdd(out + (size_t)tok * H_DIM + c, g * v);
            }
        }
    }
}

// ---------------- aux loss ----------------
__global__ void aux_kernel(float* __restrict__ out) {
    float sumA = 0.f, sumF = 0.f;
    for (int e = 0; e < N_EXP; e++) {
        sumA += fabsf(g_accp[e]);
        sumF += fabsf((float)g_counts[e]);
    }
    float sw = 0.f;
    for (int e = 0; e < N_EXP; e++)
        sw += (g_accp[e] / sumA) * ((float)g_counts[e] / sumF);
    sw *= (float)N_EXP;
    float z = g_zsum / (float)T_TOKENS;
    out[AUX_OFF] = sw + 0.1f * z;
}

// ---------------- launch ----------------
extern "C" void kernel_launch(void* const* d_in, const int* in_sizes, int n_in,
                              void* d_out, int out_size) {
    const float* x      = (const float*)d_in[0];
    const float* wg     = (const float*)d_in[1];
    const float* w_fc   = (const float*)d_in[2];
    const float* b_fc   = (const float*)d_in[3];
    const float* w_proj = (const float*)d_in[4];
    const float* b_proj = (const float*)d_in[5];
    float* out = (float*)d_out;

    cudaMemsetAsync(out, 0, (size_t)OUT_ELEMS * sizeof(float), 0);
    init_kernel<<<1, 32>>>();
    router_kernel<<<T_TOKENS, 128>>>(x, wg, out);
    build_kernel<<<1, 1>>>();
    scatter_kernel<<<T_TOKENS / 128, 128>>>();
    gemm1_kernel<<<dim3(I_DIM / BN, MAXTILES), 256>>>(x, w_fc, b_fc);
    gemm2_kernel<<<dim3(H_DIM / BN, MAXTILES), 256>>>(w_proj, b_proj, out);
    aux_kernel<<<1, 1>>>(out);
}